// round 8
// baseline (speedup 1.0000x reference)
#include <cuda_runtime.h>
#include <cuda_bf16.h>
#include <math.h>
#include <stdint.h>

#define CHANNEL   256
#define MEM_SIZE  684
#define POS_NUM   128
#define NEG_NUM   512
#define CLASS_NUM 60
#define BANK_ROWS 41040          // MEM_SIZE * CLASS_NUM
#define BANK_PAD  41088          // 321 * 128
#define BATCH     512
#define SEL_T     512
#define CAP       2048

// ---------------- scratch (static device globals) ------------------------------
__device__ __nv_bfloat16 g_bank_bf[(size_t)BANK_PAD * CHANNEL];   // 21 MB
__device__ __nv_bfloat16 g_f_bf[(size_t)BATCH * CHANNEL];
__device__ float  g_flag[BANK_ROWS];
__device__ float  g_ap[(size_t)BATCH * BANK_ROWS];                // 84 MB
__device__ double g_partial[BATCH];

// ---------------- helpers ------------------------------------------------------
__device__ __forceinline__ uint32_t smem_u32(const void* p) {
    uint32_t a;
    asm("{ .reg .u64 t; cvta.to.shared.u64 t, %1; cvt.u32.u64 %0, t; }" : "=r"(a) : "l"(p));
    return a;
}
__device__ __forceinline__ unsigned key_asc(float x) {
    unsigned u = __float_as_uint(x);
    return (u & 0x80000000u) ? ~u : (u | 0x80000000u);
}
__device__ __forceinline__ float key_dec(unsigned k) {
    unsigned u = (k & 0x80000000u) ? (k ^ 0x80000000u) : ~k;
    return __uint_as_float(u);
}
// warp-aggregated histogram increment (kills same-bucket serialization)
__device__ __forceinline__ void aggInc(int* hist, unsigned b) {
    unsigned am = __activemask();
    unsigned same = __match_any_sync(am, b);
    int lead = __ffs(same) - 1;
    if ((int)(threadIdx.x & 31) == lead) atomicAdd(&hist[b], __popc(same));
}

// ---------------- prep: bank -> bf16 (padded), flag copy, f -> bf16 ------------
__global__ void convert_kernel(const float* __restrict__ bank,
                               const float* __restrict__ flag,
                               const float* __restrict__ f) {
    size_t tid = (size_t)blockIdx.x * blockDim.x + threadIdx.x;
    size_t stride = (size_t)gridDim.x * blockDim.x;
    size_t total4 = (size_t)BANK_PAD * CHANNEL / 4;
    size_t real4  = (size_t)BANK_ROWS * CHANNEL / 4;
    for (size_t i = tid; i < total4; i += stride) {
        float4 v = make_float4(0.f, 0.f, 0.f, 0.f);
        if (i < real4) v = ((const float4*)bank)[i];
        __nv_bfloat162 lo(__float2bfloat16(v.x), __float2bfloat16(v.y));
        __nv_bfloat162 hi(__float2bfloat16(v.z), __float2bfloat16(v.w));
        ((__nv_bfloat162*)g_bank_bf)[2 * i]     = lo;
        ((__nv_bfloat162*)g_bank_bf)[2 * i + 1] = hi;
    }
    for (size_t i = tid; i < BANK_ROWS; i += stride) g_flag[i] = flag[i];
    size_t f4 = (size_t)BATCH * CHANNEL / 4;
    for (size_t i = tid; i < f4; i += stride) {
        float4 v = ((const float4*)f)[i];
        __nv_bfloat162 lo(__float2bfloat16(v.x), __float2bfloat16(v.y));
        __nv_bfloat162 hi(__float2bfloat16(v.z), __float2bfloat16(v.w));
        ((__nv_bfloat162*)g_f_bf)[2 * i]     = lo;
        ((__nv_bfloat162*)g_f_bf)[2 * i + 1] = hi;
    }
}

__global__ void scatter_kernel(const float* __restrict__ f, const int* __restrict__ idx) {
    int n = blockIdx.x;
    int r = idx[n];
    float4 v = ((const float4*)(f + (size_t)n * CHANNEL))[threadIdx.x];
    __nv_bfloat162 lo(__float2bfloat16(v.x), __float2bfloat16(v.y));
    __nv_bfloat162 hi(__float2bfloat16(v.z), __float2bfloat16(v.w));
    __nv_bfloat162* dst = (__nv_bfloat162*)(g_bank_bf + (size_t)r * CHANNEL) + 2 * threadIdx.x;
    dst[0] = lo; dst[1] = hi;
    if (threadIdx.x == 0) g_flag[r] = 1.0f;
}

// ---------------- mma.sync bf16 GEMM (unchanged from R7) -----------------------
#define SMEM_STRIDE 72
__global__ void __launch_bounds__(256, 2) gemm_mma_kernel() {
    __shared__ __nv_bfloat16 As[128][SMEM_STRIDE];
    __shared__ __nv_bfloat16 Bs[128][SMEM_STRIDE];
    int tid = threadIdx.x, lane = tid & 31, wid = tid >> 5;
    int wm = wid >> 2, wn = wid & 3;
    int bm = blockIdx.y * 128, bn = blockIdx.x * 128;
    const __nv_bfloat16* Ag = g_f_bf    + (size_t)bm * CHANNEL;
    const __nv_bfloat16* Bg = g_bank_bf + (size_t)bn * CHANNEL;
    float acc[4][4][4];
#pragma unroll
    for (int i = 0; i < 4; i++)
#pragma unroll
        for (int j = 0; j < 4; j++)
#pragma unroll
            for (int k = 0; k < 4; k++) acc[i][j][k] = 0.f;
    int lrow = tid >> 3, lcol = (tid & 7) * 8;
#pragma unroll
    for (int kc = 0; kc < 4; kc++) {
        int k0 = kc * 64;
#pragma unroll
        for (int it = 0; it < 4; it++) {
            int row = lrow + it * 32;
            *(uint4*)&As[row][lcol] = *(const uint4*)(Ag + (size_t)row * CHANNEL + k0 + lcol);
            *(uint4*)&Bs[row][lcol] = *(const uint4*)(Bg + (size_t)row * CHANNEL + k0 + lcol);
        }
        __syncthreads();
#pragma unroll
        for (int ks = 0; ks < 4; ks++) {
            int kk = ks * 16;
            uint32_t af[4][4], bfr[4][2];
#pragma unroll
            for (int mt = 0; mt < 4; mt++) {
                int row = wm * 64 + mt * 16 + (lane & 15);
                int col = kk + (lane >> 4) * 8;
                uint32_t a = smem_u32(&As[row][col]);
                asm volatile("ldmatrix.sync.aligned.m8n8.x4.shared.b16 {%0,%1,%2,%3}, [%4];"
                    : "=r"(af[mt][0]), "=r"(af[mt][1]), "=r"(af[mt][2]), "=r"(af[mt][3]) : "r"(a));
            }
#pragma unroll
            for (int g = 0; g < 2; g++) {
                int ntile = g * 2 + (lane >> 4);
                int khalf = (lane >> 3) & 1;
                int row = wn * 32 + ntile * 8 + (lane & 7);
                int col = kk + khalf * 8;
                uint32_t a = smem_u32(&Bs[row][col]);
                uint32_t b0, b1, b2, b3;
                asm volatile("ldmatrix.sync.aligned.m8n8.x4.shared.b16 {%0,%1,%2,%3}, [%4];"
                    : "=r"(b0), "=r"(b1), "=r"(b2), "=r"(b3) : "r"(a));
                bfr[g * 2][0] = b0; bfr[g * 2][1] = b1;
                bfr[g * 2 + 1][0] = b2; bfr[g * 2 + 1][1] = b3;
            }
#pragma unroll
            for (int mt = 0; mt < 4; mt++)
#pragma unroll
                for (int nt = 0; nt < 4; nt++) {
                    asm volatile(
                        "mma.sync.aligned.m16n8k16.row.col.f32.bf16.bf16.f32 "
                        "{%0,%1,%2,%3}, {%4,%5,%6,%7}, {%8,%9}, {%0,%1,%2,%3};"
                        : "+f"(acc[mt][nt][0]), "+f"(acc[mt][nt][1]),
                          "+f"(acc[mt][nt][2]), "+f"(acc[mt][nt][3])
                        : "r"(af[mt][0]), "r"(af[mt][1]), "r"(af[mt][2]), "r"(af[mt][3]),
                          "r"(bfr[nt][0]), "r"(bfr[nt][1]));
                }
        }
        __syncthreads();
    }
    int r0 = lane >> 2, c0 = (lane & 3) * 2;
#pragma unroll
    for (int mt = 0; mt < 4; mt++) {
        int row = bm + wm * 64 + mt * 16 + r0;
#pragma unroll
        for (int nt = 0; nt < 4; nt++) {
            int col = bn + wn * 32 + nt * 8 + c0;
            if (col < BANK_ROWS) {
                float* d = g_ap + (size_t)row * BANK_ROWS + col;
                *(float2*)d = make_float2(acc[mt][nt][0], acc[mt][nt][1]);
                *(float2*)(d + (size_t)8 * BANK_ROWS) = make_float2(acc[mt][nt][2], acc[mt][nt][3]);
            }
        }
    }
}

// ---------------- selection -----------------------------------------------------
__device__ __forceinline__ void pick_bucket(const int* hist, int nb, int kk,
                                            int* s_coarse, int* s_b, int* s_kk) {
    int tid = threadIdx.x;
    int chunk = nb >> 8;
    if (tid < 256) {
        int part = 0;
        for (int j = 0; j < chunk; j++) part += hist[tid * chunk + j];
        s_coarse[tid] = part;
    }
    __syncthreads();
    if (tid == 0) {
        int cum = 0, cb = 0;
        for (; cb < 255; cb++) {
            if (cum + s_coarse[cb] >= kk) break;
            cum += s_coarse[cb];
        }
        int b = cb * chunk;
        for (;; b++) { if (cum + hist[b] >= kk) break; cum += hist[b]; }
        *s_b = b; *s_kk = kk - cum;
    }
    __syncthreads();
}

// radix-select over a small smem candidate array; returns full 32-bit threshold key
__device__ unsigned cand_radix(const unsigned* cand, int cnt, int kk0, int shift0,
                               unsigned pref0, int* hist, int* s_coarse,
                               int* s_b, int* s_kk, int* need_out) {
    int tid = threadIdx.x;
    unsigned pref = pref0;
    int shift = shift0, kk = kk0;
    while (shift > 0) {
        int bits = (shift >= 11) ? 11 : shift;
        int nsh = shift - bits;
        int nb = 1 << bits;
        __syncthreads();
        for (int i = tid; i < nb; i += SEL_T) hist[i] = 0;
        __syncthreads();
        for (int j = tid; j < cnt; j += SEL_T) {
            unsigned k = cand[j];
            unsigned hi = (shift >= 32) ? 0u : (k >> shift);
            if (hi == pref) atomicAdd(&hist[(k >> nsh) & (nb - 1)], 1);
        }
        __syncthreads();
        pick_bucket(hist, nb, kk, s_coarse, s_b, s_kk);
        pref = (pref << bits) | (unsigned)(*s_b);
        kk = *s_kk;
        shift = nsh;
        __syncthreads();
    }
    *need_out = kk;
    return pref;
}

__device__ double block_red(double v, double* s_warp) {
#pragma unroll
    for (int o = 16; o; o >>= 1) v += __shfl_down_sync(0xffffffffu, v, o);
    int w = threadIdx.x >> 5;
    if ((threadIdx.x & 31) == 0) s_warp[w] = v;
    __syncthreads();
    double r = 0;
    if (threadIdx.x == 0) for (int i = 0; i < 16; i++) r += s_warp[i];
    __syncthreads();
    return r;
}

#define NW_MASK ((BANK_ROWS + 31) / 32)

__global__ void __launch_bounds__(SEL_T) select_kernel(const int* __restrict__ label,
                                                       const float* __restrict__ rand_neg) {
    __shared__ int      histA[2048];
    __shared__ int      hb_ch[2048];     // histB during level-1, candH after
    __shared__ unsigned candRk[CAP];
    __shared__ int      candRi[CAP];
    __shared__ unsigned s_mask[NW_MASK];
    __shared__ unsigned s_posk[MEM_SIZE];
    __shared__ int      s_coarse[256];
    __shared__ float    s_posv[POS_NUM];
    __shared__ int      s_tie[256];
    __shared__ double   s_warp[16];
    __shared__ int      s_b, s_kk, s_cntH, s_cntR, s_tc;
    __shared__ double   s_Sh, s_Sr;

    int n = blockIdx.x;
    int tid = threadIdx.x;
    int lab = label[n];
    const float* ap  = g_ap + (size_t)n * BANK_ROWS;
    const float* rnd = rand_neg + (size_t)n * BANK_ROWS;
    const float4* ap4  = (const float4*)ap;
    const float4* rnd4 = (const float4*)rnd;
    const int NV4 = BANK_ROWS / 4;

    // ---- valid bitmask + clear level-1 histograms ----
    for (int w = tid; w < NW_MASK; w += SEL_T) {
        unsigned m = 0;
        int base = w * 32;
        int lim = BANK_ROWS - base; if (lim > 32) lim = 32;
        for (int e = 0; e < lim; e++) {
            int i = base + e;
            if ((i % CLASS_NUM) != lab && g_flag[i] > 0.f) m |= (1u << e);
        }
        s_mask[w] = m;
    }
    for (int i = tid; i < 2048; i += SEL_T) { histA[i] = 0; hb_ch[i] = 0; }
    __syncthreads();

    // ---- fused level-1 histogram scan (hard keys -> histA, rand keys -> hb_ch) ----
    for (int j = tid; j < NV4; j += SEL_T) {
        float4 a = ap4[j];
        float4 r = rnd4[j];
        int base = j * 4;
        unsigned mb = (s_mask[base >> 5] >> (base & 31)) & 0xFu;
        float av[4] = {a.x, a.y, a.z, a.w};
        float rv[4] = {r.x, r.y, r.z, r.w};
#pragma unroll
        for (int e = 0; e < 4; e++) {
            if ((mb >> e) & 1u) {
                aggInc(histA, (~key_asc(av[e])) >> 21);
                aggInc(hb_ch, key_asc(rv[e]) >> 21);
            }
        }
    }
    __syncthreads();

    // ---- pick level-1 buckets ----
    pick_bucket(histA, 2048, NEG_NUM, s_coarse, &s_b, &s_kk);
    unsigned prefH = (unsigned)s_b; int kkH = s_kk; int cntH_lvl = histA[s_b]; int shiftH = 21;
    __syncthreads();
    pick_bucket(hb_ch, 2048, NEG_NUM, s_coarse, &s_b, &s_kk);
    unsigned prefR = (unsigned)s_b; int kkR = s_kk; int cntR_lvl = hb_ch[s_b]; int shiftR = 21;
    __syncthreads();

    // ---- rare refinement (exactness guarantee when a bucket exceeds CAP) ----
    while (cntH_lvl > CAP && shiftH > 0) {
        int bits = (shiftH >= 11) ? 11 : shiftH;
        int nsh = shiftH - bits;
        int nb = 1 << bits;
        __syncthreads();
        for (int i = tid; i < nb; i += SEL_T) histA[i] = 0;
        __syncthreads();
        for (int j = tid; j < NV4; j += SEL_T) {
            float4 a = ap4[j];
            int base = j * 4;
            unsigned mb = (s_mask[base >> 5] >> (base & 31)) & 0xFu;
            float av[4] = {a.x, a.y, a.z, a.w};
#pragma unroll
            for (int e = 0; e < 4; e++)
                if ((mb >> e) & 1u) {
                    unsigned k = ~key_asc(av[e]);
                    if ((k >> shiftH) == prefH) aggInc(histA, (k >> nsh) & (nb - 1));
                }
        }
        __syncthreads();
        pick_bucket(histA, nb, kkH, s_coarse, &s_b, &s_kk);
        prefH = (prefH << bits) | (unsigned)s_b;
        kkH = s_kk; cntH_lvl = histA[s_b]; shiftH = nsh;
        __syncthreads();
    }
    while (cntR_lvl > CAP && shiftR > 0) {
        int bits = (shiftR >= 11) ? 11 : shiftR;
        int nsh = shiftR - bits;
        int nb = 1 << bits;
        __syncthreads();
        for (int i = tid; i < nb; i += SEL_T) histA[i] = 0;
        __syncthreads();
        for (int j = tid; j < NV4; j += SEL_T) {
            float4 r = rnd4[j];
            int base = j * 4;
            unsigned mb = (s_mask[base >> 5] >> (base & 31)) & 0xFu;
            float rv[4] = {r.x, r.y, r.z, r.w};
#pragma unroll
            for (int e = 0; e < 4; e++)
                if ((mb >> e) & 1u) {
                    unsigned k = key_asc(rv[e]);
                    if ((k >> shiftR) == prefR) aggInc(histA, (k >> nsh) & (nb - 1));
                }
        }
        __syncthreads();
        pick_bucket(histA, nb, kkR, s_coarse, &s_b, &s_kk);
        prefR = (prefR << bits) | (unsigned)s_b;
        kkR = s_kk; cntR_lvl = histA[s_b]; shiftR = nsh;
        __syncthreads();
    }

    // ---- fused compact scan: sum strictly-above-bucket + collect candidates ----
    unsigned* candH = (unsigned*)hb_ch;       // histB dead; reuse as candH
    if (tid == 0) { s_cntH = 0; s_cntR = 0; }
    __syncthreads();
    unsigned KbH = prefH << shiftH;
    unsigned KbR = prefR << shiftR;
    double sumH = 0.0, sumR = 0.0;
    for (int j = tid; j < NV4; j += SEL_T) {
        float4 a = ap4[j];
        float4 r = rnd4[j];
        int base = j * 4;
        unsigned mb = (s_mask[base >> 5] >> (base & 31)) & 0xFu;
        float av[4] = {a.x, a.y, a.z, a.w};
        float rv[4] = {r.x, r.y, r.z, r.w};
#pragma unroll
        for (int e = 0; e < 4; e++) {
            if (!((mb >> e) & 1u)) continue;
            float v = av[e];
            unsigned kh = ~key_asc(v);
            if (kh < KbH) sumH += (double)expf(v);
            else if ((kh >> shiftH) == prefH) {
                int p = atomicAdd(&s_cntH, 1);
                if (p < CAP) candH[p] = kh;
            }
            unsigned kr = key_asc(rv[e]);
            if (kr < KbR) sumR += (double)expf(v);
            else if ((kr >> shiftR) == prefR) {
                int p = atomicAdd(&s_cntR, 1);
                if (p < CAP) { candRk[p] = kr; candRi[p] = base + e; }
            }
        }
    }
    __syncthreads();
    int cH = s_cntH < CAP ? s_cntH : CAP;
    int cR = s_cntR < CAP ? s_cntR : CAP;

    // ---- finish hard: in-smem radix over candidates ----
    int needH;
    unsigned Th = cand_radix(candH, cH, kkH, shiftH, prefH, histA, s_coarse, &s_b, &s_kk, &needH);
    for (int j = tid; j < cH; j += SEL_T) {
        unsigned k = candH[j];
        if (k < Th) sumH += (double)expf(key_dec(~k));
    }
    double Sh = block_red(sumH, s_warp);
    if (tid == 0) s_Sh = Sh + (double)needH * (double)expf(key_dec(~Th));
    __syncthreads();

    // ---- finish rand ----
    int needR;
    unsigned Tr = cand_radix(candRk, cR, kkR, shiftR, prefR, histA, s_coarse, &s_b, &s_kk, &needR);
    if (tid == 0) s_tc = 0;
    __syncthreads();
    for (int j = tid; j < cR; j += SEL_T) {
        unsigned k = candRk[j];
        if (k < Tr) sumR += (double)expf(ap[candRi[j]]);
        else if (k == Tr) {
            int p = atomicAdd(&s_tc, 1);
            if (p < 256) s_tie[p] = candRi[j];
        }
    }
    __syncthreads();
    double Sr = block_red(sumR, s_warp);
    if (tid == 0) {
        int c = s_tc < 256 ? s_tc : 256;
        int take = needR < c ? needR : c;
        double add = 0.0;
        for (int t = 0; t < take; t++) {          // smallest column indices first
            int best = 0x7fffffff, bi = -1;
            for (int j = 0; j < c; j++)
                if (s_tie[j] >= 0 && s_tie[j] < best) { best = s_tie[j]; bi = j; }
            s_tie[bi] = -1;
            add += (double)expf(ap[best]);
        }
        s_Sr = Sr + add;
    }
    __syncthreads();

    // ---- positives: fully in smem ----
    for (int i = tid; i < MEM_SIZE; i += SEL_T) {
        int m = lab + CLASS_NUM * i;
        s_posk[i] = (g_flag[m] > 0.f) ? key_asc(ap[m]) : 0xFFFFFFFFu;
    }
    __syncthreads();
    int needP;
    unsigned Tp = cand_radix(s_posk, MEM_SIZE, POS_NUM, 32, 0u, histA, s_coarse, &s_b, &s_kk, &needP);
    if (tid == 0) s_tc = 0;
    __syncthreads();
    for (int i = tid; i < MEM_SIZE; i += SEL_T) {
        unsigned k = s_posk[i];
        if (k < Tp) {
            int p = atomicAdd(&s_tc, 1);
            s_posv[p] = key_dec(k);
        }
    }
    __syncthreads();
    if (tid == 0) {
        float tv = key_dec(Tp);
        int base = s_tc;                          // == POS_NUM - needP
        for (int t = 0; t < needP; t++) s_posv[base + t] = tv;
    }
    __syncthreads();

    // ---- loss partial ----
    double Shv = s_Sh, Srv = s_Sr;
    double l = 0.0;
    if (tid < POS_NUM) {
        double p = (double)s_posv[tid];
        double ep = exp(p);
        l = 2.0 * p - log(ep + Shv) - log(ep + Srv);
    }
    double tot = block_red(l, s_warp);
    if (tid == 0) g_partial[n] = tot;
}

// ---------------- finalize ------------------------------------------------------
__global__ void finalize_kernel(float* __restrict__ out) {
    __shared__ double s_warp[16];
    int tid = threadIdx.x;
    double v = g_partial[tid];
#pragma unroll
    for (int o = 16; o; o >>= 1) v += __shfl_down_sync(0xffffffffu, v, o);
    if ((tid & 31) == 0) s_warp[tid >> 5] = v;
    __syncthreads();
    if (tid == 0) {
        double t = 0;
        for (int i = 0; i < 16; i++) t += s_warp[i];
        out[0] = (float)(-t / (double)(BATCH * 2 * POS_NUM));
    }
}

// ---------------- launch --------------------------------------------------------
extern "C" void kernel_launch(void* const* d_in, const int* in_sizes, int n_in,
                              void* d_out, int out_size) {
    const float* f        = (const float*)d_in[0];
    const int*   label    = (const int*)d_in[1];
    const int*   enq      = (const int*)d_in[2];
    const float* bank     = (const float*)d_in[3];
    const float* flag     = (const float*)d_in[4];
    const float* rand_neg = (const float*)d_in[5];
    float* out = (float*)d_out;

    convert_kernel<<<1024, 256>>>(bank, flag, f);
    scatter_kernel<<<BATCH, 64>>>(f, enq);
    dim3 g(BANK_PAD / 128, BATCH / 128);
    gemm_mma_kernel<<<g, 256>>>();
    select_kernel<<<BATCH, SEL_T>>>(label, rand_neg);
    finalize_kernel<<<1, 512>>>(out);
}

// round 9
// speedup vs baseline: 1.3421x; 1.3421x over previous
#include <cuda_runtime.h>
#include <cuda_bf16.h>
#include <math.h>
#include <stdint.h>

#define CHANNEL   256
#define MEM_SIZE  684
#define POS_NUM   128
#define NEG_NUM   512
#define CLASS_NUM 60
#define BANK_ROWS 41040          // MEM_SIZE * CLASS_NUM
#define BANK_PAD  41088          // 321 * 128
#define BATCH     512
#define SEL_T     256
#define CAP       2048
#define NW_MASK   ((BANK_ROWS + 31) / 32)

// ---------------- scratch (static device globals) ------------------------------
__device__ __nv_bfloat16 g_bank_bf[(size_t)BANK_PAD * CHANNEL];   // 21 MB
__device__ __nv_bfloat16 g_f_bf[(size_t)BATCH * CHANNEL];
__device__ float  g_flag[BANK_ROWS];
__device__ float  g_ap[(size_t)BATCH * BANK_ROWS];                // 84 MB
__device__ unsigned g_masks[CLASS_NUM][NW_MASK];                  // 308 KB
__device__ double g_partial[BATCH];

// ---------------- helpers ------------------------------------------------------
__device__ __forceinline__ uint32_t smem_u32(const void* p) {
    uint32_t a;
    asm("{ .reg .u64 t; cvta.to.shared.u64 t, %1; cvt.u32.u64 %0, t; }" : "=r"(a) : "l"(p));
    return a;
}
__device__ __forceinline__ unsigned key_asc(float x) {
    unsigned u = __float_as_uint(x);
    return (u & 0x80000000u) ? ~u : (u | 0x80000000u);
}
__device__ __forceinline__ float key_dec(unsigned k) {
    unsigned u = (k & 0x80000000u) ? (k ^ 0x80000000u) : ~k;
    return __uint_as_float(u);
}
__device__ __forceinline__ void aggInc(int* hist, unsigned b) {
    unsigned am = __activemask();
    unsigned same = __match_any_sync(am, b);
    int lead = __ffs(same) - 1;
    if ((int)(threadIdx.x & 31) == lead) atomicAdd(&hist[b], __popc(same));
}

// ---------------- prep kernels --------------------------------------------------
__global__ void convert_kernel(const float* __restrict__ bank,
                               const float* __restrict__ flag,
                               const float* __restrict__ f) {
    size_t tid = (size_t)blockIdx.x * blockDim.x + threadIdx.x;
    size_t stride = (size_t)gridDim.x * blockDim.x;
    size_t total4 = (size_t)BANK_PAD * CHANNEL / 4;
    size_t real4  = (size_t)BANK_ROWS * CHANNEL / 4;
    for (size_t i = tid; i < total4; i += stride) {
        float4 v = make_float4(0.f, 0.f, 0.f, 0.f);
        if (i < real4) v = ((const float4*)bank)[i];
        __nv_bfloat162 lo(__float2bfloat16(v.x), __float2bfloat16(v.y));
        __nv_bfloat162 hi(__float2bfloat16(v.z), __float2bfloat16(v.w));
        ((__nv_bfloat162*)g_bank_bf)[2 * i]     = lo;
        ((__nv_bfloat162*)g_bank_bf)[2 * i + 1] = hi;
    }
    for (size_t i = tid; i < BANK_ROWS; i += stride) g_flag[i] = flag[i];
    size_t f4 = (size_t)BATCH * CHANNEL / 4;
    for (size_t i = tid; i < f4; i += stride) {
        float4 v = ((const float4*)f)[i];
        __nv_bfloat162 lo(__float2bfloat16(v.x), __float2bfloat16(v.y));
        __nv_bfloat162 hi(__float2bfloat16(v.z), __float2bfloat16(v.w));
        ((__nv_bfloat162*)g_f_bf)[2 * i]     = lo;
        ((__nv_bfloat162*)g_f_bf)[2 * i + 1] = hi;
    }
}

__global__ void scatter_kernel(const float* __restrict__ f, const int* __restrict__ idx) {
    int n = blockIdx.x;
    int r = idx[n];
    float4 v = ((const float4*)(f + (size_t)n * CHANNEL))[threadIdx.x];
    __nv_bfloat162 lo(__float2bfloat16(v.x), __float2bfloat16(v.y));
    __nv_bfloat162 hi(__float2bfloat16(v.z), __float2bfloat16(v.w));
    __nv_bfloat162* dst = (__nv_bfloat162*)(g_bank_bf + (size_t)r * CHANNEL) + 2 * threadIdx.x;
    dst[0] = lo; dst[1] = hi;
    if (threadIdx.x == 0) g_flag[r] = 1.0f;
}

// per-label valid bitmask (runs after scatter)
__global__ void mask_kernel() {
    int lab = blockIdx.x;
    for (int w = threadIdx.x; w < NW_MASK; w += blockDim.x) {
        unsigned m = 0;
        int base = w * 32;
        int lim = BANK_ROWS - base; if (lim > 32) lim = 32;
        for (int e = 0; e < lim; e++) {
            int i = base + e;
            if ((i % CLASS_NUM) != lab && g_flag[i] > 0.f) m |= (1u << e);
        }
        g_masks[lab][w] = m;
    }
}

// ---------------- mma.sync bf16 GEMM (unchanged) -------------------------------
#define SMEM_STRIDE 72
__global__ void __launch_bounds__(256, 2) gemm_mma_kernel() {
    __shared__ __nv_bfloat16 As[128][SMEM_STRIDE];
    __shared__ __nv_bfloat16 Bs[128][SMEM_STRIDE];
    int tid = threadIdx.x, lane = tid & 31, wid = tid >> 5;
    int wm = wid >> 2, wn = wid & 3;
    int bm = blockIdx.y * 128, bn = blockIdx.x * 128;
    const __nv_bfloat16* Ag = g_f_bf    + (size_t)bm * CHANNEL;
    const __nv_bfloat16* Bg = g_bank_bf + (size_t)bn * CHANNEL;
    float acc[4][4][4];
#pragma unroll
    for (int i = 0; i < 4; i++)
#pragma unroll
        for (int j = 0; j < 4; j++)
#pragma unroll
            for (int k = 0; k < 4; k++) acc[i][j][k] = 0.f;
    int lrow = tid >> 3, lcol = (tid & 7) * 8;
#pragma unroll
    for (int kc = 0; kc < 4; kc++) {
        int k0 = kc * 64;
#pragma unroll
        for (int it = 0; it < 4; it++) {
            int row = lrow + it * 32;
            *(uint4*)&As[row][lcol] = *(const uint4*)(Ag + (size_t)row * CHANNEL + k0 + lcol);
            *(uint4*)&Bs[row][lcol] = *(const uint4*)(Bg + (size_t)row * CHANNEL + k0 + lcol);
        }
        __syncthreads();
#pragma unroll
        for (int ks = 0; ks < 4; ks++) {
            int kk = ks * 16;
            uint32_t af[4][4], bfr[4][2];
#pragma unroll
            for (int mt = 0; mt < 4; mt++) {
                int row = wm * 64 + mt * 16 + (lane & 15);
                int col = kk + (lane >> 4) * 8;
                uint32_t a = smem_u32(&As[row][col]);
                asm volatile("ldmatrix.sync.aligned.m8n8.x4.shared.b16 {%0,%1,%2,%3}, [%4];"
                    : "=r"(af[mt][0]), "=r"(af[mt][1]), "=r"(af[mt][2]), "=r"(af[mt][3]) : "r"(a));
            }
#pragma unroll
            for (int g = 0; g < 2; g++) {
                int ntile = g * 2 + (lane >> 4);
                int khalf = (lane >> 3) & 1;
                int row = wn * 32 + ntile * 8 + (lane & 7);
                int col = kk + khalf * 8;
                uint32_t a = smem_u32(&Bs[row][col]);
                uint32_t b0, b1, b2, b3;
                asm volatile("ldmatrix.sync.aligned.m8n8.x4.shared.b16 {%0,%1,%2,%3}, [%4];"
                    : "=r"(b0), "=r"(b1), "=r"(b2), "=r"(b3) : "r"(a));
                bfr[g * 2][0] = b0; bfr[g * 2][1] = b1;
                bfr[g * 2 + 1][0] = b2; bfr[g * 2 + 1][1] = b3;
            }
#pragma unroll
            for (int mt = 0; mt < 4; mt++)
#pragma unroll
                for (int nt = 0; nt < 4; nt++) {
                    asm volatile(
                        "mma.sync.aligned.m16n8k16.row.col.f32.bf16.bf16.f32 "
                        "{%0,%1,%2,%3}, {%4,%5,%6,%7}, {%8,%9}, {%0,%1,%2,%3};"
                        : "+f"(acc[mt][nt][0]), "+f"(acc[mt][nt][1]),
                          "+f"(acc[mt][nt][2]), "+f"(acc[mt][nt][3])
                        : "r"(af[mt][0]), "r"(af[mt][1]), "r"(af[mt][2]), "r"(af[mt][3]),
                          "r"(bfr[nt][0]), "r"(bfr[nt][1]));
                }
        }
        __syncthreads();
    }
    int r0 = lane >> 2, c0 = (lane & 3) * 2;
#pragma unroll
    for (int mt = 0; mt < 4; mt++) {
        int row = bm + wm * 64 + mt * 16 + r0;
#pragma unroll
        for (int nt = 0; nt < 4; nt++) {
            int col = bn + wn * 32 + nt * 8 + c0;
            if (col < BANK_ROWS) {
                float* d = g_ap + (size_t)row * BANK_ROWS + col;
                *(float2*)d = make_float2(acc[mt][nt][0], acc[mt][nt][1]);
                *(float2*)(d + (size_t)8 * BANK_ROWS) = make_float2(acc[mt][nt][2], acc[mt][nt][3]);
            }
        }
    }
}

// ---------------- selection helpers --------------------------------------------
__device__ __forceinline__ void pick_bucket(const int* hist, int nb, int kk,
                                            int* s_coarse, int* s_b, int* s_kk) {
    int tid = threadIdx.x;
    int chunk = (nb >> 8) ? (nb >> 8) : 1;
    int nc = nb / chunk;
    if (tid < nc) {
        int part = 0;
        for (int j = 0; j < chunk; j++) part += hist[tid * chunk + j];
        s_coarse[tid] = part;
    }
    __syncthreads();
    if (tid == 0) {
        int cum = 0, cb = 0;
        for (; cb < nc - 1; cb++) {
            if (cum + s_coarse[cb] >= kk) break;
            cum += s_coarse[cb];
        }
        int b = cb * chunk;
        for (;; b++) { if (cum + hist[b] >= kk) break; cum += hist[b]; }
        *s_b = b; *s_kk = kk - cum;
    }
    __syncthreads();
}

__device__ unsigned cand_radix(const unsigned* cand, int cnt, int kk0, int shift0,
                               unsigned pref0, int* hist, int* s_coarse,
                               int* s_b, int* s_kk, int* need_out) {
    int tid = threadIdx.x;
    unsigned pref = pref0;
    int shift = shift0, kk = kk0;
    while (shift > 0) {
        int bits = (shift >= 11) ? 11 : shift;
        int nsh = shift - bits;
        int nb = 1 << bits;
        __syncthreads();
        for (int i = tid; i < nb; i += SEL_T) hist[i] = 0;
        __syncthreads();
        for (int j = tid; j < cnt; j += SEL_T) {
            unsigned k = cand[j];
            unsigned hi = (shift >= 32) ? 0u : (k >> shift);
            if (hi == pref) atomicAdd(&hist[(k >> nsh) & (nb - 1)], 1);
        }
        __syncthreads();
        pick_bucket(hist, nb, kk, s_coarse, s_b, s_kk);
        pref = (pref << bits) | (unsigned)(*s_b);
        kk = *s_kk;
        shift = nsh;
        __syncthreads();
    }
    *need_out = kk;
    return pref;
}

__device__ double block_red(double v, double* s_warp) {
#pragma unroll
    for (int o = 16; o; o >>= 1) v += __shfl_down_sync(0xffffffffu, v, o);
    int w = threadIdx.x >> 5;
    if ((threadIdx.x & 31) == 0) s_warp[w] = v;
    __syncthreads();
    double r = 0;
    if (threadIdx.x == 0) for (int i = 0; i < (SEL_T / 32); i++) r += s_warp[i];
    __syncthreads();
    return r;
}

// ---------------- per-row selection + loss partial -----------------------------
__global__ void __launch_bounds__(SEL_T, 4) select_kernel(const int* __restrict__ label,
                                                          const float* __restrict__ rand_neg) {
    __shared__ int      histA[2048];
    __shared__ int      hb_ch[2048];     // histB during level-1, candH after
    __shared__ unsigned candRk[CAP];
    __shared__ int      candRi[CAP];
    __shared__ unsigned s_mask[NW_MASK];
    __shared__ unsigned s_posk[MEM_SIZE];
    __shared__ int      s_coarse[256];
    __shared__ float    s_posv[POS_NUM];
    __shared__ int      s_tie[256];
    __shared__ double   s_warp[SEL_T / 32];
    __shared__ int      s_b, s_kk, s_cntH, s_cntR, s_tc;
    __shared__ double   s_Sh, s_Sr;

    int n = blockIdx.x;
    int tid = threadIdx.x;
    int lab = label[n];
    const float* ap  = g_ap + (size_t)n * BANK_ROWS;
    const float* rnd = rand_neg + (size_t)n * BANK_ROWS;
    const float4* ap4  = (const float4*)ap;
    const float4* rnd4 = (const float4*)rnd;
    const int NV4 = BANK_ROWS / 4;         // 10260
    const int CH = SEL_T * 4;              // 1024 float4 per unrolled iter
    const int NFULL = NV4 / CH;            // 10

    // ---- load precomputed mask + clear level-1 histograms ----
    for (int w = tid; w < NW_MASK; w += SEL_T) s_mask[w] = g_masks[lab][w];
    for (int i = tid; i < 2048; i += SEL_T) { histA[i] = 0; hb_ch[i] = 0; }
    __syncthreads();

    // ---- fused level-1 histogram scan, 4x unrolled (MLP=8) ----
    {
        int j = tid;
        for (int it = 0; it < NFULL; it++, j += CH) {
            float4 a0 = ap4[j], a1 = ap4[j + SEL_T], a2 = ap4[j + 2 * SEL_T], a3 = ap4[j + 3 * SEL_T];
            float4 r0 = rnd4[j], r1 = rnd4[j + SEL_T], r2 = rnd4[j + 2 * SEL_T], r3 = rnd4[j + 3 * SEL_T];
            float4 aa[4] = {a0, a1, a2, a3};
            float4 rr[4] = {r0, r1, r2, r3};
#pragma unroll
            for (int u = 0; u < 4; u++) {
                int base = (j + u * SEL_T) * 4;
                unsigned mb = (s_mask[base >> 5] >> (base & 31)) & 0xFu;
                float av[4] = {aa[u].x, aa[u].y, aa[u].z, aa[u].w};
                float rv[4] = {rr[u].x, rr[u].y, rr[u].z, rr[u].w};
#pragma unroll
                for (int e = 0; e < 4; e++) {
                    if ((mb >> e) & 1u) {
                        aggInc(histA, (~key_asc(av[e])) >> 21);
                        aggInc(hb_ch, key_asc(rv[e]) >> 21);
                    }
                }
            }
        }
        for (int jj = NFULL * CH + tid; jj < NV4; jj += SEL_T) {
            float4 a = ap4[jj];
            float4 r = rnd4[jj];
            int base = jj * 4;
            unsigned mb = (s_mask[base >> 5] >> (base & 31)) & 0xFu;
            float av[4] = {a.x, a.y, a.z, a.w};
            float rv[4] = {r.x, r.y, r.z, r.w};
#pragma unroll
            for (int e = 0; e < 4; e++) {
                if ((mb >> e) & 1u) {
                    aggInc(histA, (~key_asc(av[e])) >> 21);
                    aggInc(hb_ch, key_asc(rv[e]) >> 21);
                }
            }
        }
    }
    __syncthreads();

    // ---- pick level-1 buckets ----
    pick_bucket(histA, 2048, NEG_NUM, s_coarse, &s_b, &s_kk);
    unsigned prefH = (unsigned)s_b; int kkH = s_kk; int cntH_lvl = histA[s_b]; int shiftH = 21;
    __syncthreads();
    pick_bucket(hb_ch, 2048, NEG_NUM, s_coarse, &s_b, &s_kk);
    unsigned prefR = (unsigned)s_b; int kkR = s_kk; int cntR_lvl = hb_ch[s_b]; int shiftR = 21;
    __syncthreads();

    // ---- rare refinement (only when a bucket exceeds CAP) ----
    while (cntH_lvl > CAP && shiftH > 0) {
        int bits = (shiftH >= 11) ? 11 : shiftH;
        int nsh = shiftH - bits;
        int nb = 1 << bits;
        __syncthreads();
        for (int i = tid; i < nb; i += SEL_T) histA[i] = 0;
        __syncthreads();
        for (int j = tid; j < NV4; j += SEL_T) {
            float4 a = ap4[j];
            int base = j * 4;
            unsigned mb = (s_mask[base >> 5] >> (base & 31)) & 0xFu;
            float av[4] = {a.x, a.y, a.z, a.w};
#pragma unroll
            for (int e = 0; e < 4; e++)
                if ((mb >> e) & 1u) {
                    unsigned k = ~key_asc(av[e]);
                    if ((k >> shiftH) == prefH) aggInc(histA, (k >> nsh) & (nb - 1));
                }
        }
        __syncthreads();
        pick_bucket(histA, nb, kkH, s_coarse, &s_b, &s_kk);
        prefH = (prefH << bits) | (unsigned)s_b;
        kkH = s_kk; cntH_lvl = histA[s_b]; shiftH = nsh;
        __syncthreads();
    }
    while (cntR_lvl > CAP && shiftR > 0) {
        int bits = (shiftR >= 11) ? 11 : shiftR;
        int nsh = shiftR - bits;
        int nb = 1 << bits;
        __syncthreads();
        for (int i = tid; i < nb; i += SEL_T) histA[i] = 0;
        __syncthreads();
        for (int j = tid; j < NV4; j += SEL_T) {
            float4 r = rnd4[j];
            int base = j * 4;
            unsigned mb = (s_mask[base >> 5] >> (base & 31)) & 0xFu;
            float rv[4] = {r.x, r.y, r.z, r.w};
#pragma unroll
            for (int e = 0; e < 4; e++)
                if ((mb >> e) & 1u) {
                    unsigned k = key_asc(rv[e]);
                    if ((k >> shiftR) == prefR) aggInc(histA, (k >> nsh) & (nb - 1));
                }
        }
        __syncthreads();
        pick_bucket(histA, nb, kkR, s_coarse, &s_b, &s_kk);
        prefR = (prefR << bits) | (unsigned)s_b;
        kkR = s_kk; cntR_lvl = histA[s_b]; shiftR = nsh;
        __syncthreads();
    }

    // ---- fused compact scan (4x unrolled): sums above bucket + candidates -----
    unsigned* candH = (unsigned*)hb_ch;
    if (tid == 0) { s_cntH = 0; s_cntR = 0; }
    __syncthreads();
    unsigned KbH = prefH << shiftH;
    unsigned KbR = prefR << shiftR;
    double sumH = 0.0, sumR = 0.0;
    {
        int j = tid;
        for (int it = 0; it < NFULL; it++, j += CH) {
            float4 a0 = ap4[j], a1 = ap4[j + SEL_T], a2 = ap4[j + 2 * SEL_T], a3 = ap4[j + 3 * SEL_T];
            float4 r0 = rnd4[j], r1 = rnd4[j + SEL_T], r2 = rnd4[j + 2 * SEL_T], r3 = rnd4[j + 3 * SEL_T];
            float4 aa[4] = {a0, a1, a2, a3};
            float4 rr[4] = {r0, r1, r2, r3};
#pragma unroll
            for (int u = 0; u < 4; u++) {
                int base = (j + u * SEL_T) * 4;
                unsigned mb = (s_mask[base >> 5] >> (base & 31)) & 0xFu;
                float av[4] = {aa[u].x, aa[u].y, aa[u].z, aa[u].w};
                float rv[4] = {rr[u].x, rr[u].y, rr[u].z, rr[u].w};
#pragma unroll
                for (int e = 0; e < 4; e++) {
                    if (!((mb >> e) & 1u)) continue;
                    float v = av[e];
                    unsigned kh = ~key_asc(v);
                    if (kh < KbH) sumH += (double)__expf(v);
                    else if ((kh >> shiftH) == prefH) {
                        int p = atomicAdd(&s_cntH, 1);
                        if (p < CAP) candH[p] = kh;
                    }
                    unsigned kr = key_asc(rv[e]);
                    if (kr < KbR) sumR += (double)__expf(v);
                    else if ((kr >> shiftR) == prefR) {
                        int p = atomicAdd(&s_cntR, 1);
                        if (p < CAP) { candRk[p] = kr; candRi[p] = base + e; }
                    }
                }
            }
        }
        for (int jj = NFULL * CH + tid; jj < NV4; jj += SEL_T) {
            float4 a = ap4[jj];
            float4 r = rnd4[jj];
            int base = jj * 4;
            unsigned mb = (s_mask[base >> 5] >> (base & 31)) & 0xFu;
            float av[4] = {a.x, a.y, a.z, a.w};
            float rv[4] = {r.x, r.y, r.z, r.w};
#pragma unroll
            for (int e = 0; e < 4; e++) {
                if (!((mb >> e) & 1u)) continue;
                float v = av[e];
                unsigned kh = ~key_asc(v);
                if (kh < KbH) sumH += (double)__expf(v);
                else if ((kh >> shiftH) == prefH) {
                    int p = atomicAdd(&s_cntH, 1);
                    if (p < CAP) candH[p] = kh;
                }
                unsigned kr = key_asc(rv[e]);
                if (kr < KbR) sumR += (double)__expf(v);
                else if ((kr >> shiftR) == prefR) {
                    int p = atomicAdd(&s_cntR, 1);
                    if (p < CAP) { candRk[p] = kr; candRi[p] = base + e; }
                }
            }
        }
    }
    __syncthreads();
    int cH = s_cntH < CAP ? s_cntH : CAP;
    int cR = s_cntR < CAP ? s_cntR : CAP;

    // ---- finish hard ----
    int needH;
    unsigned Th = cand_radix(candH, cH, kkH, shiftH, prefH, histA, s_coarse, &s_b, &s_kk, &needH);
    for (int j = tid; j < cH; j += SEL_T) {
        unsigned k = candH[j];
        if (k < Th) sumH += (double)__expf(key_dec(~k));
    }
    double Sh = block_red(sumH, s_warp);
    if (tid == 0) s_Sh = Sh + (double)needH * (double)__expf(key_dec(~Th));
    __syncthreads();

    // ---- finish rand ----
    int needR;
    unsigned Tr = cand_radix(candRk, cR, kkR, shiftR, prefR, histA, s_coarse, &s_b, &s_kk, &needR);
    if (tid == 0) s_tc = 0;
    __syncthreads();
    for (int j = tid; j < cR; j += SEL_T) {
        unsigned k = candRk[j];
        if (k < Tr) sumR += (double)__expf(ap[candRi[j]]);
        else if (k == Tr) {
            int p = atomicAdd(&s_tc, 1);
            if (p < 256) s_tie[p] = candRi[j];
        }
    }
    __syncthreads();
    double Sr = block_red(sumR, s_warp);
    if (tid == 0) {
        int c = s_tc < 256 ? s_tc : 256;
        int take = needR < c ? needR : c;
        double add = 0.0;
        for (int t = 0; t < take; t++) {          // smallest column indices first
            int best = 0x7fffffff, bi = -1;
            for (int j = 0; j < c; j++)
                if (s_tie[j] >= 0 && s_tie[j] < best) { best = s_tie[j]; bi = j; }
            s_tie[bi] = -1;
            add += (double)__expf(ap[best]);
        }
        s_Sr = Sr + add;
    }
    __syncthreads();

    // ---- positives: fully in smem ----
    for (int i = tid; i < MEM_SIZE; i += SEL_T) {
        int m = lab + CLASS_NUM * i;
        s_posk[i] = (g_flag[m] > 0.f) ? key_asc(ap[m]) : 0xFFFFFFFFu;
    }
    __syncthreads();
    int needP;
    unsigned Tp = cand_radix(s_posk, MEM_SIZE, POS_NUM, 32, 0u, histA, s_coarse, &s_b, &s_kk, &needP);
    if (tid == 0) s_tc = 0;
    __syncthreads();
    for (int i = tid; i < MEM_SIZE; i += SEL_T) {
        unsigned k = s_posk[i];
        if (k < Tp) {
            int p = atomicAdd(&s_tc, 1);
            s_posv[p] = key_dec(k);
        }
    }
    __syncthreads();
    if (tid == 0) {
        float tv = key_dec(Tp);
        int base = s_tc;
        for (int t = 0; t < needP; t++) s_posv[base + t] = tv;
    }
    __syncthreads();

    // ---- loss partial ----
    double Shv = s_Sh, Srv = s_Sr;
    double l = 0.0;
    if (tid < POS_NUM) {
        double p = (double)s_posv[tid];
        double ep = exp(p);
        l = 2.0 * p - log(ep + Shv) - log(ep + Srv);
    }
    double tot = block_red(l, s_warp);
    if (tid == 0) g_partial[n] = tot;
}

// ---------------- finalize ------------------------------------------------------
__global__ void finalize_kernel(float* __restrict__ out) {
    __shared__ double s_warp[16];
    int tid = threadIdx.x;
    double v = g_partial[tid];
#pragma unroll
    for (int o = 16; o; o >>= 1) v += __shfl_down_sync(0xffffffffu, v, o);
    if ((tid & 31) == 0) s_warp[tid >> 5] = v;
    __syncthreads();
    if (tid == 0) {
        double t = 0;
        for (int i = 0; i < 16; i++) t += s_warp[i];
        out[0] = (float)(-t / (double)(BATCH * 2 * POS_NUM));
    }
}

// ---------------- launch --------------------------------------------------------
extern "C" void kernel_launch(void* const* d_in, const int* in_sizes, int n_in,
                              void* d_out, int out_size) {
    const float* f        = (const float*)d_in[0];
    const int*   label    = (const int*)d_in[1];
    const int*   enq      = (const int*)d_in[2];
    const float* bank     = (const float*)d_in[3];
    const float* flag     = (const float*)d_in[4];
    const float* rand_neg = (const float*)d_in[5];
    float* out = (float*)d_out;

    convert_kernel<<<1024, 256>>>(bank, flag, f);
    scatter_kernel<<<BATCH, 64>>>(f, enq);
    mask_kernel<<<CLASS_NUM, 256>>>();
    dim3 g(BANK_PAD / 128, BATCH / 128);
    gemm_mma_kernel<<<g, 256>>>();
    select_kernel<<<BATCH, SEL_T>>>(label, rand_neg);
    finalize_kernel<<<1, 512>>>(out);
}

// round 10
// speedup vs baseline: 2.3996x; 1.7880x over previous
#include <cuda_runtime.h>
#include <cuda_bf16.h>
#include <math.h>
#include <stdint.h>

#define CHANNEL   256
#define MEM_SIZE  684
#define POS_NUM   128
#define NEG_NUM   512
#define CLASS_NUM 60
#define BANK_ROWS 41040          // MEM_SIZE * CLASS_NUM
#define BANK_PAD  41088          // 321 * 128
#define BATCH     512
#define SEL_T     256
#define CAP       1792
#define NW_MASK   ((BANK_ROWS + 31) / 32)
#define TH_HARD   0.115f         // conservative value filter for top-512 hard negs
#define TH_RAND   0.02f          // conservative filter for 512 smallest uniforms

// ---------------- scratch (static device globals) ------------------------------
__device__ __nv_bfloat16 g_bank_bf[(size_t)BANK_PAD * CHANNEL];   // 21 MB
__device__ __nv_bfloat16 g_f_bf[(size_t)BATCH * CHANNEL];
__device__ float  g_flag[BANK_ROWS];
__device__ float  g_ap[(size_t)BATCH * BANK_ROWS];                // 84 MB
__device__ unsigned g_masks[CLASS_NUM][NW_MASK];                  // 308 KB
__device__ double g_partial[BATCH];

// ---------------- helpers ------------------------------------------------------
__device__ __forceinline__ uint32_t smem_u32(const void* p) {
    uint32_t a;
    asm("{ .reg .u64 t; cvta.to.shared.u64 t, %1; cvt.u32.u64 %0, t; }" : "=r"(a) : "l"(p));
    return a;
}
__device__ __forceinline__ unsigned key_asc(float x) {
    unsigned u = __float_as_uint(x);
    return (u & 0x80000000u) ? ~u : (u | 0x80000000u);
}
__device__ __forceinline__ float key_dec(unsigned k) {
    unsigned u = (k & 0x80000000u) ? (k ^ 0x80000000u) : ~k;
    return __uint_as_float(u);
}
__device__ __forceinline__ void aggInc(int* hist, unsigned b) {
    unsigned am = __activemask();
    unsigned same = __match_any_sync(am, b);
    int lead = __ffs(same) - 1;
    if ((int)(threadIdx.x & 31) == lead) atomicAdd(&hist[b], __popc(same));
}

// ---------------- prep kernels --------------------------------------------------
__global__ void convert_kernel(const float* __restrict__ bank,
                               const float* __restrict__ flag,
                               const float* __restrict__ f) {
    size_t tid = (size_t)blockIdx.x * blockDim.x + threadIdx.x;
    size_t stride = (size_t)gridDim.x * blockDim.x;
    size_t total4 = (size_t)BANK_PAD * CHANNEL / 4;
    size_t real4  = (size_t)BANK_ROWS * CHANNEL / 4;
    for (size_t i = tid; i < total4; i += stride) {
        float4 v = make_float4(0.f, 0.f, 0.f, 0.f);
        if (i < real4) v = ((const float4*)bank)[i];
        __nv_bfloat162 lo(__float2bfloat16(v.x), __float2bfloat16(v.y));
        __nv_bfloat162 hi(__float2bfloat16(v.z), __float2bfloat16(v.w));
        ((__nv_bfloat162*)g_bank_bf)[2 * i]     = lo;
        ((__nv_bfloat162*)g_bank_bf)[2 * i + 1] = hi;
    }
    for (size_t i = tid; i < BANK_ROWS; i += stride) g_flag[i] = flag[i];
    size_t f4 = (size_t)BATCH * CHANNEL / 4;
    for (size_t i = tid; i < f4; i += stride) {
        float4 v = ((const float4*)f)[i];
        __nv_bfloat162 lo(__float2bfloat16(v.x), __float2bfloat16(v.y));
        __nv_bfloat162 hi(__float2bfloat16(v.z), __float2bfloat16(v.w));
        ((__nv_bfloat162*)g_f_bf)[2 * i]     = lo;
        ((__nv_bfloat162*)g_f_bf)[2 * i + 1] = hi;
    }
}

__global__ void scatter_kernel(const float* __restrict__ f, const int* __restrict__ idx) {
    int n = blockIdx.x;
    int r = idx[n];
    float4 v = ((const float4*)(f + (size_t)n * CHANNEL))[threadIdx.x];
    __nv_bfloat162 lo(__float2bfloat16(v.x), __float2bfloat16(v.y));
    __nv_bfloat162 hi(__float2bfloat16(v.z), __float2bfloat16(v.w));
    __nv_bfloat162* dst = (__nv_bfloat162*)(g_bank_bf + (size_t)r * CHANNEL) + 2 * threadIdx.x;
    dst[0] = lo; dst[1] = hi;
    if (threadIdx.x == 0) g_flag[r] = 1.0f;
}

__global__ void mask_kernel() {
    int lab = blockIdx.x;
    for (int w = threadIdx.x; w < NW_MASK; w += blockDim.x) {
        unsigned m = 0;
        int base = w * 32;
        int lim = BANK_ROWS - base; if (lim > 32) lim = 32;
        for (int e = 0; e < lim; e++) {
            int i = base + e;
            if ((i % CLASS_NUM) != lab && g_flag[i] > 0.f) m |= (1u << e);
        }
        g_masks[lab][w] = m;
    }
}

// ---------------- mma.sync bf16 GEMM (unchanged) -------------------------------
#define SMEM_STRIDE 72
__global__ void __launch_bounds__(256, 2) gemm_mma_kernel() {
    __shared__ __nv_bfloat16 As[128][SMEM_STRIDE];
    __shared__ __nv_bfloat16 Bs[128][SMEM_STRIDE];
    int tid = threadIdx.x, lane = tid & 31, wid = tid >> 5;
    int wm = wid >> 2, wn = wid & 3;
    int bm = blockIdx.y * 128, bn = blockIdx.x * 128;
    const __nv_bfloat16* Ag = g_f_bf    + (size_t)bm * CHANNEL;
    const __nv_bfloat16* Bg = g_bank_bf + (size_t)bn * CHANNEL;
    float acc[4][4][4];
#pragma unroll
    for (int i = 0; i < 4; i++)
#pragma unroll
        for (int j = 0; j < 4; j++)
#pragma unroll
            for (int k = 0; k < 4; k++) acc[i][j][k] = 0.f;
    int lrow = tid >> 3, lcol = (tid & 7) * 8;
#pragma unroll
    for (int kc = 0; kc < 4; kc++) {
        int k0 = kc * 64;
#pragma unroll
        for (int it = 0; it < 4; it++) {
            int row = lrow + it * 32;
            *(uint4*)&As[row][lcol] = *(const uint4*)(Ag + (size_t)row * CHANNEL + k0 + lcol);
            *(uint4*)&Bs[row][lcol] = *(const uint4*)(Bg + (size_t)row * CHANNEL + k0 + lcol);
        }
        __syncthreads();
#pragma unroll
        for (int ks = 0; ks < 4; ks++) {
            int kk = ks * 16;
            uint32_t af[4][4], bfr[4][2];
#pragma unroll
            for (int mt = 0; mt < 4; mt++) {
                int row = wm * 64 + mt * 16 + (lane & 15);
                int col = kk + (lane >> 4) * 8;
                uint32_t a = smem_u32(&As[row][col]);
                asm volatile("ldmatrix.sync.aligned.m8n8.x4.shared.b16 {%0,%1,%2,%3}, [%4];"
                    : "=r"(af[mt][0]), "=r"(af[mt][1]), "=r"(af[mt][2]), "=r"(af[mt][3]) : "r"(a));
            }
#pragma unroll
            for (int g = 0; g < 2; g++) {
                int ntile = g * 2 + (lane >> 4);
                int khalf = (lane >> 3) & 1;
                int row = wn * 32 + ntile * 8 + (lane & 7);
                int col = kk + khalf * 8;
                uint32_t a = smem_u32(&Bs[row][col]);
                uint32_t b0, b1, b2, b3;
                asm volatile("ldmatrix.sync.aligned.m8n8.x4.shared.b16 {%0,%1,%2,%3}, [%4];"
                    : "=r"(b0), "=r"(b1), "=r"(b2), "=r"(b3) : "r"(a));
                bfr[g * 2][0] = b0; bfr[g * 2][1] = b1;
                bfr[g * 2 + 1][0] = b2; bfr[g * 2 + 1][1] = b3;
            }
#pragma unroll
            for (int mt = 0; mt < 4; mt++)
#pragma unroll
                for (int nt = 0; nt < 4; nt++) {
                    asm volatile(
                        "mma.sync.aligned.m16n8k16.row.col.f32.bf16.bf16.f32 "
                        "{%0,%1,%2,%3}, {%4,%5,%6,%7}, {%8,%9}, {%0,%1,%2,%3};"
                        : "+f"(acc[mt][nt][0]), "+f"(acc[mt][nt][1]),
                          "+f"(acc[mt][nt][2]), "+f"(acc[mt][nt][3])
                        : "r"(af[mt][0]), "r"(af[mt][1]), "r"(af[mt][2]), "r"(af[mt][3]),
                          "r"(bfr[nt][0]), "r"(bfr[nt][1]));
                }
        }
        __syncthreads();
    }
    int r0 = lane >> 2, c0 = (lane & 3) * 2;
#pragma unroll
    for (int mt = 0; mt < 4; mt++) {
        int row = bm + wm * 64 + mt * 16 + r0;
#pragma unroll
        for (int nt = 0; nt < 4; nt++) {
            int col = bn + wn * 32 + nt * 8 + c0;
            if (col < BANK_ROWS) {
                float* d = g_ap + (size_t)row * BANK_ROWS + col;
                *(float2*)d = make_float2(acc[mt][nt][0], acc[mt][nt][1]);
                *(float2*)(d + (size_t)8 * BANK_ROWS) = make_float2(acc[mt][nt][2], acc[mt][nt][3]);
            }
        }
    }
}

// ---------------- selection helpers --------------------------------------------
__device__ __forceinline__ void pick_bucket(const int* hist, int nb, int kk,
                                            int* s_coarse, int* s_b, int* s_kk) {
    int tid = threadIdx.x;
    int chunk = (nb >> 8) ? (nb >> 8) : 1;
    int nc = nb / chunk;
    if (tid < nc) {
        int part = 0;
        for (int j = 0; j < chunk; j++) part += hist[tid * chunk + j];
        s_coarse[tid] = part;
    }
    __syncthreads();
    if (tid == 0) {
        int cum = 0, cb = 0;
        for (; cb < nc - 1; cb++) {
            if (cum + s_coarse[cb] >= kk) break;
            cum += s_coarse[cb];
        }
        int b = cb * chunk;
        for (;; b++) { if (cum + hist[b] >= kk) break; cum += hist[b]; }
        *s_b = b; *s_kk = kk - cum;
    }
    __syncthreads();
}

// exact radix select over an smem candidate array -> full 32-bit threshold key
__device__ unsigned cand_radix(const unsigned* cand, int cnt, int kk0, int shift0,
                               unsigned pref0, int* hist, int* s_coarse,
                               int* s_b, int* s_kk, int* need_out) {
    int tid = threadIdx.x;
    unsigned pref = pref0;
    int shift = shift0, kk = kk0;
    while (shift > 0) {
        int bits = (shift >= 11) ? 11 : shift;
        int nsh = shift - bits;
        int nb = 1 << bits;
        __syncthreads();
        for (int i = tid; i < nb; i += SEL_T) hist[i] = 0;
        __syncthreads();
        for (int j = tid; j < cnt; j += SEL_T) {
            unsigned k = cand[j];
            unsigned hi = (shift >= 32) ? 0u : (k >> shift);
            if (hi == pref) atomicAdd(&hist[(k >> nsh) & (nb - 1)], 1);
        }
        __syncthreads();
        pick_bucket(hist, nb, kk, s_coarse, s_b, s_kk);
        pref = (pref << bits) | (unsigned)(*s_b);
        kk = *s_kk;
        shift = nsh;
        __syncthreads();
    }
    *need_out = kk;
    return pref;
}

// exact fallback: full global radix (mode 0 = hard keys over ap, 1 = rand keys)
__device__ unsigned glob_radix(int mode, const float* __restrict__ ap,
                               const float* __restrict__ rnd,
                               const unsigned* __restrict__ s_mask,
                               int K, int* hist, int* s_coarse,
                               int* s_b, int* s_kk, int* p_need) {
    int tid = threadIdx.x;
    unsigned prefix = 0;
    int kk = K, shift = 32;
    for (int pass = 0; pass < 3; pass++) {
        int bits = (pass < 2) ? 11 : 10;
        shift -= bits;
        int nb = 1 << bits;
        __syncthreads();
        for (int i = tid; i < nb; i += SEL_T) hist[i] = 0;
        __syncthreads();
        for (int i = tid; i < BANK_ROWS; i += SEL_T) {
            bool valid = (s_mask[i >> 5] >> (i & 31)) & 1u;
            unsigned key = 0xFFFFFFFFu;
            if (valid) key = (mode == 0) ? ~key_asc(ap[i]) : key_asc(rnd[i]);
            if (pass == 0 || (key >> (shift + bits)) == prefix)
                aggInc(hist, (key >> shift) & (nb - 1));
        }
        __syncthreads();
        pick_bucket(hist, nb, kk, s_coarse, s_b, s_kk);
        prefix = (prefix << bits) | (unsigned)(*s_b);
        kk = *s_kk;
        __syncthreads();
    }
    *p_need = kk;
    return prefix;
}

__device__ double block_red(double v, double* s_warp) {
#pragma unroll
    for (int o = 16; o; o >>= 1) v += __shfl_down_sync(0xffffffffu, v, o);
    int w = threadIdx.x >> 5;
    if ((threadIdx.x & 31) == 0) s_warp[w] = v;
    __syncthreads();
    double r = 0;
    if (threadIdx.x == 0) for (int i = 0; i < (SEL_T / 32); i++) r += s_warp[i];
    __syncthreads();
    return r;
}

#define MBIT(i) ((s_mask[(i) >> 5] >> ((i) & 31)) & 1u)

// ---------------- per-row selection + loss partial -----------------------------
__global__ void __launch_bounds__(SEL_T, 4) select_kernel(const int* __restrict__ label,
                                                          const float* __restrict__ rand_neg) {
    __shared__ unsigned s_mask[NW_MASK];
    __shared__ unsigned candHk[CAP];
    __shared__ int      candHi[CAP];
    __shared__ unsigned candRk[CAP];
    __shared__ int      candRi[CAP];
    __shared__ int      hist[2048];
    __shared__ unsigned s_posk[MEM_SIZE];
    __shared__ int      s_coarse[256];
    __shared__ float    s_posv[POS_NUM];
    __shared__ int      s_tie[256];
    __shared__ double   s_warp[SEL_T / 32];
    __shared__ int      s_b, s_kk, s_cntH, s_cntR, s_tc;
    __shared__ double   s_Sh, s_Sr;

    int n = blockIdx.x;
    int tid = threadIdx.x;
    int lab = label[n];
    const float* ap  = g_ap + (size_t)n * BANK_ROWS;
    const float* rnd = rand_neg + (size_t)n * BANK_ROWS;
    const float4* ap4  = (const float4*)ap;
    const float4* rnd4 = (const float4*)rnd;
    const int NV4 = BANK_ROWS / 4;         // 10260
    const int CH = SEL_T * 4;              // 1024 float4 per unrolled iter
    const int NFULL = NV4 / CH;            // 10

    for (int w = tid; w < NW_MASK; w += SEL_T) s_mask[w] = g_masks[lab][w];
    if (tid == 0) { s_cntH = 0; s_cntR = 0; }
    __syncthreads();

    // ===== single fused filter scan (no masks, no keys in hot path) =====
    {
        int j = tid;
        for (int it = 0; it < NFULL; it++, j += CH) {
            float4 a0 = ap4[j], a1 = ap4[j + SEL_T], a2 = ap4[j + 2 * SEL_T], a3 = ap4[j + 3 * SEL_T];
            float4 r0 = rnd4[j], r1 = rnd4[j + SEL_T], r2 = rnd4[j + 2 * SEL_T], r3 = rnd4[j + 3 * SEL_T];
            float4 aa[4] = {a0, a1, a2, a3};
            float4 rr[4] = {r0, r1, r2, r3};
#pragma unroll
            for (int u = 0; u < 4; u++) {
                int base = (j + u * SEL_T) * 4;
                float av[4] = {aa[u].x, aa[u].y, aa[u].z, aa[u].w};
                float rv[4] = {rr[u].x, rr[u].y, rr[u].z, rr[u].w};
#pragma unroll
                for (int e = 0; e < 4; e++) {
                    if (av[e] > TH_HARD) {
                        int p = atomicAdd(&s_cntH, 1);
                        if (p < CAP) { candHk[p] = ~key_asc(av[e]); candHi[p] = base + e; }
                    }
                    if (rv[e] < TH_RAND) {
                        int p = atomicAdd(&s_cntR, 1);
                        if (p < CAP) { candRk[p] = key_asc(rv[e]); candRi[p] = base + e; }
                    }
                }
            }
        }
        for (int jj = NFULL * CH + tid; jj < NV4; jj += SEL_T) {
            float4 a = ap4[jj];
            float4 r = rnd4[jj];
            int base = jj * 4;
            float av[4] = {a.x, a.y, a.z, a.w};
            float rv[4] = {r.x, r.y, r.z, r.w};
#pragma unroll
            for (int e = 0; e < 4; e++) {
                if (av[e] > TH_HARD) {
                    int p = atomicAdd(&s_cntH, 1);
                    if (p < CAP) { candHk[p] = ~key_asc(av[e]); candHi[p] = base + e; }
                }
                if (rv[e] < TH_RAND) {
                    int p = atomicAdd(&s_cntR, 1);
                    if (p < CAP) { candRk[p] = key_asc(rv[e]); candRi[p] = base + e; }
                }
            }
        }
    }
    __syncthreads();
    int rawH = s_cntH, rawR = s_cntR;

    // ===== hard negatives =====
    // compact valid candidates (keys only) through hist scratch
    if (tid == 0) s_tc = 0;
    __syncthreads();
    {
        int lim = rawH < CAP ? rawH : CAP;
        for (int j = tid; j < lim; j += SEL_T) {
            int idx = candHi[j];
            if (MBIT(idx)) {
                int p = atomicAdd(&s_tc, 1);
                ((unsigned*)hist)[p] = candHk[j];
            }
        }
    }
    __syncthreads();
    int vH = s_tc;
    for (int j = tid; j < vH; j += SEL_T) candHk[j] = ((unsigned*)hist)[j];
    __syncthreads();

    if (rawH <= CAP && vH >= NEG_NUM) {
        // fast path: exact select + sum over candidates in smem
        int needH;
        unsigned Th = cand_radix(candHk, vH, NEG_NUM, 32, 0u, hist, s_coarse, &s_b, &s_kk, &needH);
        double sumH = 0.0;
        for (int j = tid; j < vH; j += SEL_T) {
            unsigned k = candHk[j];
            if (k < Th) sumH += (double)__expf(key_dec(~k));
        }
        double Sh = block_red(sumH, s_warp);
        if (tid == 0) s_Sh = Sh + (double)needH * (double)__expf(key_dec(~Th));
    } else {
        // exact fallback: full global radix + sum scan
        int needH;
        unsigned Th = glob_radix(0, ap, rnd, s_mask, NEG_NUM, hist, s_coarse, &s_b, &s_kk, &needH);
        double sumH = 0.0;
        for (int i = tid; i < BANK_ROWS; i += SEL_T) {
            if (MBIT(i)) {
                float v = ap[i];
                if (~key_asc(v) < Th) sumH += (double)__expf(v);
            }
        }
        double Sh = block_red(sumH, s_warp);
        if (tid == 0) s_Sh = Sh + (double)needH * (double)__expf(key_dec(~Th));
    }
    __syncthreads();

    // ===== random negatives =====
    // compact valid (key,idx) pairs; hist + candHi (free now) as scratch
    if (tid == 0) s_tc = 0;
    __syncthreads();
    {
        int lim = rawR < CAP ? rawR : CAP;
        for (int j = tid; j < lim; j += SEL_T) {
            int idx = candRi[j];
            if (MBIT(idx)) {
                int p = atomicAdd(&s_tc, 1);
                ((unsigned*)hist)[p] = candRk[j];
                candHi[p] = idx;
            }
        }
    }
    __syncthreads();
    int vR = s_tc;
    for (int j = tid; j < vR; j += SEL_T) { candRk[j] = ((unsigned*)hist)[j]; candRi[j] = candHi[j]; }
    __syncthreads();

    if (rawR <= CAP && vR >= NEG_NUM) {
        int needR;
        unsigned Tr = cand_radix(candRk, vR, NEG_NUM, 32, 0u, hist, s_coarse, &s_b, &s_kk, &needR);
        if (tid == 0) s_tc = 0;
        __syncthreads();
        double sumR = 0.0;
        for (int j = tid; j < vR; j += SEL_T) {
            unsigned k = candRk[j];
            if (k < Tr) sumR += (double)__expf(ap[candRi[j]]);
            else if (k == Tr) {
                int p = atomicAdd(&s_tc, 1);
                if (p < 256) s_tie[p] = candRi[j];
            }
        }
        __syncthreads();
        double Sr = block_red(sumR, s_warp);
        if (tid == 0) {
            int c = s_tc < 256 ? s_tc : 256;
            int take = needR < c ? needR : c;
            double add = 0.0;
            for (int t = 0; t < take; t++) {          // smallest column indices first
                int best = 0x7fffffff, bi = -1;
                for (int j = 0; j < c; j++)
                    if (s_tie[j] >= 0 && s_tie[j] < best) { best = s_tie[j]; bi = j; }
                s_tie[bi] = -1;
                add += (double)__expf(ap[best]);
            }
            s_Sr = Sr + add;
        }
    } else {
        int needR;
        unsigned Tr = glob_radix(1, ap, rnd, s_mask, NEG_NUM, hist, s_coarse, &s_b, &s_kk, &needR);
        if (tid == 0) s_tc = 0;
        __syncthreads();
        double sumR = 0.0;
        for (int i = tid; i < BANK_ROWS; i += SEL_T) {
            if (MBIT(i)) {
                unsigned kr = key_asc(rnd[i]);
                if (kr < Tr) sumR += (double)__expf(ap[i]);
                else if (kr == Tr) {
                    int p = atomicAdd(&s_tc, 1);
                    if (p < 256) s_tie[p] = i;
                }
            }
        }
        __syncthreads();
        double Sr = block_red(sumR, s_warp);
        if (tid == 0) {
            int c = s_tc < 256 ? s_tc : 256;
            int take = needR < c ? needR : c;
            double add = 0.0;
            for (int t = 0; t < take; t++) {
                int best = 0x7fffffff, bi = -1;
                for (int j = 0; j < c; j++)
                    if (s_tie[j] >= 0 && s_tie[j] < best) { best = s_tie[j]; bi = j; }
                s_tie[bi] = -1;
                add += (double)__expf(ap[best]);
            }
            s_Sr = Sr + add;
        }
    }
    __syncthreads();

    // ===== positives: fully in smem =====
    for (int i = tid; i < MEM_SIZE; i += SEL_T) {
        int m = lab + CLASS_NUM * i;
        s_posk[i] = (g_flag[m] > 0.f) ? key_asc(ap[m]) : 0xFFFFFFFFu;
    }
    __syncthreads();
    int needP;
    unsigned Tp = cand_radix(s_posk, MEM_SIZE, POS_NUM, 32, 0u, hist, s_coarse, &s_b, &s_kk, &needP);
    if (tid == 0) s_tc = 0;
    __syncthreads();
    for (int i = tid; i < MEM_SIZE; i += SEL_T) {
        unsigned k = s_posk[i];
        if (k < Tp) {
            int p = atomicAdd(&s_tc, 1);
            s_posv[p] = key_dec(k);
        }
    }
    __syncthreads();
    if (tid == 0) {
        float tv = key_dec(Tp);
        int base = s_tc;                              // == POS_NUM - needP
        for (int t = 0; t < needP; t++) s_posv[base + t] = tv;
    }
    __syncthreads();

    // ===== loss partial =====
    double Shv = s_Sh, Srv = s_Sr;
    double l = 0.0;
    if (tid < POS_NUM) {
        double p = (double)s_posv[tid];
        double ep = exp(p);
        l = 2.0 * p - log(ep + Shv) - log(ep + Srv);
    }
    double tot = block_red(l, s_warp);
    if (tid == 0) g_partial[n] = tot;
}

// ---------------- finalize ------------------------------------------------------
__global__ void finalize_kernel(float* __restrict__ out) {
    __shared__ double s_warp[16];
    int tid = threadIdx.x;
    double v = g_partial[tid];
#pragma unroll
    for (int o = 16; o; o >>= 1) v += __shfl_down_sync(0xffffffffu, v, o);
    if ((tid & 31) == 0) s_warp[tid >> 5] = v;
    __syncthreads();
    if (tid == 0) {
        double t = 0;
        for (int i = 0; i < 16; i++) t += s_warp[i];
        out[0] = (float)(-t / (double)(BATCH * 2 * POS_NUM));
    }
}

// ---------------- launch --------------------------------------------------------
extern "C" void kernel_launch(void* const* d_in, const int* in_sizes, int n_in,
                              void* d_out, int out_size) {
    const float* f        = (const float*)d_in[0];
    const int*   label    = (const int*)d_in[1];
    const int*   enq      = (const int*)d_in[2];
    const float* bank     = (const float*)d_in[3];
    const float* flag     = (const float*)d_in[4];
    const float* rand_neg = (const float*)d_in[5];
    float* out = (float*)d_out;

    convert_kernel<<<1024, 256>>>(bank, flag, f);
    scatter_kernel<<<BATCH, 64>>>(f, enq);
    mask_kernel<<<CLASS_NUM, 256>>>();
    dim3 g(BANK_PAD / 128, BATCH / 128);
    gemm_mma_kernel<<<g, 256>>>();
    select_kernel<<<BATCH, SEL_T>>>(label, rand_neg);
    finalize_kernel<<<1, 512>>>(out);
}